// round 15
// baseline (speedup 1.0000x reference)
#include <cuda_runtime.h>
#include <cstdint>

// Skeleton forward kinematics: 6d rotations -> world-space joint positions.
// angles: [B, 16, 6] f32   xyz: [1, 16, 3] f32   out: [B, 16, 3] f32
//
// Round-15: HALF-TILE staging to double occupancy. The smem buffer holds only
// 12 float4 rows (half the angles): stage joints 0-7 -> compute joints 0-7
// (pw[0..23] in registers) -> restage joints 8-15 into the SAME rows ->
// compute joints 8-15, flushing all 12 pw rows into consumed rows -> gather.
// 24.9 KB/block -> 8 blocks/SM = 32 warps (was 16). The kernel is measured
// latency-bound with every pipe < 45%; doubling warp supply is the lever.

namespace {

constexpr int NJ   = 16;
constexpr int TPB  = 128;
constexpr int PIT  = 129;                       // float4 pitch (odd -> conflict-free)
constexpr size_t SMEM_BYTES = 12 * PIT * sizeof(float4) + 48 * sizeof(float);

__device__ __forceinline__ void rot6d(const float* __restrict__ a, float R[9]) {
    float n1 = rsqrtf(a[0] * a[0] + a[1] * a[1] + a[2] * a[2]);
    float b1x = a[0] * n1, b1y = a[1] * n1, b1z = a[2] * n1;
    float d = b1x * a[3] + b1y * a[4] + b1z * a[5];
    float b2x = a[3] - d * b1x, b2y = a[4] - d * b1y, b2z = a[5] - d * b1z;
    float n2 = rsqrtf(b2x * b2x + b2y * b2y + b2z * b2z);
    b2x *= n2; b2y *= n2; b2z *= n2;
    R[0] = b1x; R[1] = b1y; R[2] = b1z;
    R[3] = b2x; R[4] = b2y; R[5] = b2z;
    R[6] = b1y * b2z - b1z * b2y;
    R[7] = b1z * b2x - b1x * b2z;
    R[8] = b1x * b2y - b1y * b2x;
}

__global__ __launch_bounds__(TPB, 8)
void skeleton_fk_v15(const float4* __restrict__ angles4,
                     const float*  __restrict__ xyz,
                     float4* __restrict__ out4)
{
    extern __shared__ float4 sa4[];                           // [12 * PIT]
    float* stv = reinterpret_cast<float*>(sa4 + 12 * PIT);    // [48]: ref0 + edges

    const int t = threadIdx.x;
    const size_t tile = (size_t)blockIdx.x * TPB;
    const float4* __restrict__ src = angles4 + tile * 24;

    // ---- Stage half 0: joints 0-7 (element float4s 0..11) ----
#pragma unroll
    for (int k = 0; k < 12; ++k) {
        int g = t + k * TPB;                 // 0..1535
        int b = g / 12;
        int r = g - b * 12;
        sa4[r * PIT + b] = __ldg(src + b * 24 + r);
    }
    // stv[0..2] = ref[0]; stv[3c+k] = ref[c] - ref[parent(c)], c = 1..15.
    {
        constexpr int PARENT[15] = {0, 1, 2, 3, 4, 3, 6, 7, 8, 9, 3, 11, 12, 13, 14};
        if (t < 3) stv[t] = __ldg(xyz + t);
        else if (t < 48) {
            int i = t - 3;
            int e = i / 3, k = i - 3 * e;
            stv[t] = __ldg(xyz + 3 * (e + 1) + k) - __ldg(xyz + 3 * PARENT[e] + k);
        }
    }
    __syncthreads();                         // S1: half 0 + stv visible

    float a2[12];
    float pw[48];
    float Rc[9], Rs[9];

    auto loadRows = [&](int r0) {            // rows r0..r0+2 -> a2[0..11]
        float4 q0 = sa4[(r0 + 0) * PIT + t];
        float4 q1 = sa4[(r0 + 1) * PIT + t];
        float4 q2 = sa4[(r0 + 2) * PIT + t];
        a2[0] = q0.x; a2[1] = q0.y; a2[2]  = q0.z; a2[3]  = q0.w;
        a2[4] = q1.x; a2[5] = q1.y; a2[6]  = q1.z; a2[7]  = q1.w;
        a2[8] = q2.x; a2[9] = q2.y; a2[10] = q2.z; a2[11] = q2.w;
    };
    auto flushRow = [&](int r) {
        sa4[r * PIT + t] = make_float4(pw[4 * r + 0], pw[4 * r + 1],
                                       pw[4 * r + 2], pw[4 * r + 3]);
    };
    auto step = [&](int p, int c, const float* a6) {
        float R[9];
        rot6d(a6, R);
        float Rn[9];
#pragma unroll
        for (int i = 0; i < 3; ++i)
#pragma unroll
            for (int k = 0; k < 3; ++k)
                Rn[3 * i + k] = Rc[3 * i + 0] * R[0 + k]
                              + Rc[3 * i + 1] * R[3 + k]
                              + Rc[3 * i + 2] * R[6 + k];
        float tx = stv[3 * c + 0], ty = stv[3 * c + 1], tz = stv[3 * c + 2];
        pw[3 * c + 0] = Rn[0] * tx + Rn[1] * ty + Rn[2] * tz + pw[3 * p + 0];
        pw[3 * c + 1] = Rn[3] * tx + Rn[4] * ty + Rn[5] * tz + pw[3 * p + 1];
        pw[3 * c + 2] = Rn[6] * tx + Rn[7] * ty + Rn[8] * tz + pw[3 * p + 2];
#pragma unroll
        for (int i = 0; i < 9; ++i) Rc[i] = Rn[i];
    };

    // ---- Phase 1: joints 0-7, pw[0..23] stays in registers ----
    loadRows(0);                             // joints 0,1
    rot6d(&a2[0], Rc);
    {
        float x = stv[0], y = stv[1], z = stv[2];
        pw[0] = Rc[0] * x + Rc[1] * y + Rc[2] * z;
        pw[1] = Rc[3] * x + Rc[4] * y + Rc[5] * z;
        pw[2] = Rc[6] * x + Rc[7] * y + Rc[8] * z;
    }
    step(0, 1, &a2[6]);
    loadRows(3);                             // joints 2,3
    step(1, 2, &a2[0]);
    step(2, 3, &a2[6]);
#pragma unroll
    for (int i = 0; i < 9; ++i) Rs[i] = Rc[i];   // Rw3

    loadRows(6);                             // joints 4,5 (branch A)
    step(3, 4, &a2[0]);
    step(4, 5, &a2[6]);

#pragma unroll
    for (int i = 0; i < 9; ++i) Rc[i] = Rs[i];
    loadRows(9);                             // joints 6,7 (branch B start)
    step(3, 6, &a2[0]);
    step(6, 7, &a2[6]);
    // Rc = Rw7 carried across the restage.

    __syncthreads();                         // S2: all half-0 reads done

    // ---- Stage half 1: joints 8-15 (element float4s 12..23) into same rows ----
#pragma unroll
    for (int k = 0; k < 12; ++k) {
        int g = t + k * TPB;
        int b = g / 12;
        int r = g - b * 12;
        sa4[r * PIT + b] = __ldg(src + b * 24 + 12 + r);
    }
    __syncthreads();                         // S3: half 1 visible

    // ---- Phase 2: joints 8-15; flush all 12 pw rows into consumed rows ----
    loadRows(0);                             // joints 8,9
    flushRow(0); flushRow(1); flushRow(2);   // pw[0..11] -> regs freed
    step(7, 8, &a2[0]);
    step(8, 9, &a2[6]);

    loadRows(3);                             // joints 10,11
    flushRow(3); flushRow(4); flushRow(5);   // pw[12..23] -> regs freed
    step(9, 10, &a2[0]);
#pragma unroll
    for (int i = 0; i < 9; ++i) Rc[i] = Rs[i];   // branch C from Rw3
    step(3, 11, &a2[6]);

    loadRows(6);                             // joints 12,13
    flushRow(6); flushRow(7); flushRow(8);   // pw[24..35] ready
    step(11, 12, &a2[0]);
    step(12, 13, &a2[6]);

    loadRows(9);                             // joints 14,15
    flushRow(9);                             // pw[36..39] ready
    step(13, 14, &a2[0]);
    flushRow(10);                            // pw[40..43] ready
    step(14, 15, &a2[6]);
    flushRow(11);                            // pw[44..47] ready

    __syncthreads();                         // S4: pw rows complete

    // ---- Gather: conflict-free LDS.128 -> coalesced STG.128 ----
    float4* __restrict__ dst = out4 + tile * 12;
#pragma unroll
    for (int k = 0; k < 12; ++k) {
        int g = t + k * TPB;                 // 0..1535
        int b = g / 12;
        int r = g - b * 12;
        dst[g] = sa4[r * PIT + b];
    }
}

// Tail fallback (unused: 262144 % 128 == 0; kept for safety).
__global__ void skeleton_fk_tail(const float* __restrict__ angles,
                                 const float* __restrict__ xyz,
                                 float* __restrict__ out,
                                 int start, int batch)
{
    int b = start + blockIdx.x * blockDim.x + threadIdx.x;
    if (b >= batch) return;
    const float* ab = angles + (size_t)b * (NJ * 6);
    float ref[NJ * 3];
#pragma unroll
    for (int i = 0; i < NJ * 3; ++i) ref[i] = __ldg(xyz + i);

    float Rw[NJ * 9], pw[NJ * 3];
    {
        float a[6];
#pragma unroll
        for (int k = 0; k < 6; ++k) a[k] = ab[k];
        rot6d(a, &Rw[0]);
        float x = ref[0], y = ref[1], z = ref[2];
        pw[0] = Rw[0] * x + Rw[1] * y + Rw[2] * z;
        pw[1] = Rw[3] * x + Rw[4] * y + Rw[5] * z;
        pw[2] = Rw[6] * x + Rw[7] * y + Rw[8] * z;
    }
    constexpr int PARENT[15] = {0, 1, 2, 3, 4, 3, 6, 7, 8, 9, 3, 11, 12, 13, 14};
#pragma unroll
    for (int e = 0; e < 15; ++e) {
        const int p = PARENT[e], c = e + 1;
        float a[6];
#pragma unroll
        for (int k = 0; k < 6; ++k) a[k] = ab[6 * c + k];
        float R[9]; rot6d(a, R);
        float tx = ref[3 * c + 0] - ref[3 * p + 0];
        float ty = ref[3 * c + 1] - ref[3 * p + 1];
        float tz = ref[3 * c + 2] - ref[3 * p + 2];
        const float* pR = &Rw[9 * p];
        float* nR = &Rw[9 * c];
#pragma unroll
        for (int i = 0; i < 3; ++i)
#pragma unroll
            for (int k = 0; k < 3; ++k)
                nR[3 * i + k] = pR[3 * i + 0] * R[k] + pR[3 * i + 1] * R[3 + k]
                              + pR[3 * i + 2] * R[6 + k];
        pw[3 * c + 0] = nR[0] * tx + nR[1] * ty + nR[2] * tz + pw[3 * p + 0];
        pw[3 * c + 1] = nR[3] * tx + nR[4] * ty + nR[5] * tz + pw[3 * p + 1];
        pw[3 * c + 2] = nR[6] * tx + nR[7] * ty + nR[8] * tz + pw[3 * p + 2];
    }
    float* o = out + (size_t)b * (NJ * 3);
#pragma unroll
    for (int i = 0; i < NJ * 3; ++i) o[i] = pw[i];
}

}  // namespace

extern "C" void kernel_launch(void* const* d_in, const int* in_sizes, int n_in,
                              void* d_out, int out_size) {
    const float* angles = (const float*)d_in[0];
    const float* xyz    = (const float*)d_in[1];
    float* out          = (float*)d_out;

    const int batch = in_sizes[0] / (NJ * 6);
    const int full  = batch / TPB;

    cudaFuncSetAttribute(skeleton_fk_v15,
                         cudaFuncAttributeMaxDynamicSharedMemorySize,
                         (int)SMEM_BYTES);

    if (full > 0) {
        skeleton_fk_v15<<<full, TPB, SMEM_BYTES>>>(
            (const float4*)angles, xyz, (float4*)out);
    }
    const int rem = batch - full * TPB;
    if (rem > 0) {
        skeleton_fk_tail<<<(rem + 127) / 128, 128>>>(angles, xyz, out,
                                                     full * TPB, batch);
    }
}

// round 16
// speedup vs baseline: 1.3810x; 1.3810x over previous
#include <cuda_runtime.h>
#include <cstdint>

// Skeleton forward kinematics: 6d rotations -> world-space joint positions.
// angles: [B, 16, 6] f32   xyz: [1, 16, 3] f32   out: [B, 16, 3] f32
//
// Round-16: v15 half-tile staging with ONE change: __launch_bounds__(128, 6)
// instead of (128, 8). v15's 64-reg cap forced local-memory spills (L1 47.7%,
// fma down, issue down). At 6 blocks/SM the budget is 85 regs -> no spills,
// 24 warps/SM (+50% over the 16-warp plateau). Smem 24.9 KB/block.

namespace {

constexpr int NJ   = 16;
constexpr int TPB  = 128;
constexpr int PIT  = 129;                       // float4 pitch (odd -> conflict-free)
constexpr size_t SMEM_BYTES = 12 * PIT * sizeof(float4) + 48 * sizeof(float);

__device__ __forceinline__ void rot6d(const float* __restrict__ a, float R[9]) {
    float n1 = rsqrtf(a[0] * a[0] + a[1] * a[1] + a[2] * a[2]);
    float b1x = a[0] * n1, b1y = a[1] * n1, b1z = a[2] * n1;
    float d = b1x * a[3] + b1y * a[4] + b1z * a[5];
    float b2x = a[3] - d * b1x, b2y = a[4] - d * b1y, b2z = a[5] - d * b1z;
    float n2 = rsqrtf(b2x * b2x + b2y * b2y + b2z * b2z);
    b2x *= n2; b2y *= n2; b2z *= n2;
    R[0] = b1x; R[1] = b1y; R[2] = b1z;
    R[3] = b2x; R[4] = b2y; R[5] = b2z;
    R[6] = b1y * b2z - b1z * b2y;
    R[7] = b1z * b2x - b1x * b2z;
    R[8] = b1x * b2y - b1y * b2x;
}

__global__ __launch_bounds__(TPB, 6)
void skeleton_fk_v16(const float4* __restrict__ angles4,
                     const float*  __restrict__ xyz,
                     float4* __restrict__ out4)
{
    extern __shared__ float4 sa4[];                           // [12 * PIT]
    float* stv = reinterpret_cast<float*>(sa4 + 12 * PIT);    // [48]: ref0 + edges

    const int t = threadIdx.x;
    const size_t tile = (size_t)blockIdx.x * TPB;
    const float4* __restrict__ src = angles4 + tile * 24;

    // ---- Stage half 0: joints 0-7 (element float4s 0..11) ----
#pragma unroll
    for (int k = 0; k < 12; ++k) {
        int g = t + k * TPB;                 // 0..1535
        int b = g / 12;
        int r = g - b * 12;
        sa4[r * PIT + b] = __ldg(src + b * 24 + r);
    }
    // stv[0..2] = ref[0]; stv[3c+k] = ref[c] - ref[parent(c)], c = 1..15.
    {
        constexpr int PARENT[15] = {0, 1, 2, 3, 4, 3, 6, 7, 8, 9, 3, 11, 12, 13, 14};
        if (t < 3) stv[t] = __ldg(xyz + t);
        else if (t < 48) {
            int i = t - 3;
            int e = i / 3, k = i - 3 * e;
            stv[t] = __ldg(xyz + 3 * (e + 1) + k) - __ldg(xyz + 3 * PARENT[e] + k);
        }
    }
    __syncthreads();                         // S1: half 0 + stv visible

    float a2[12];
    float pw[48];
    float Rc[9], Rs[9];

    auto loadRows = [&](int r0) {            // rows r0..r0+2 -> a2[0..11]
        float4 q0 = sa4[(r0 + 0) * PIT + t];
        float4 q1 = sa4[(r0 + 1) * PIT + t];
        float4 q2 = sa4[(r0 + 2) * PIT + t];
        a2[0] = q0.x; a2[1] = q0.y; a2[2]  = q0.z; a2[3]  = q0.w;
        a2[4] = q1.x; a2[5] = q1.y; a2[6]  = q1.z; a2[7]  = q1.w;
        a2[8] = q2.x; a2[9] = q2.y; a2[10] = q2.z; a2[11] = q2.w;
    };
    auto flushRow = [&](int r) {
        sa4[r * PIT + t] = make_float4(pw[4 * r + 0], pw[4 * r + 1],
                                       pw[4 * r + 2], pw[4 * r + 3]);
    };
    auto step = [&](int p, int c, const float* a6) {
        float R[9];
        rot6d(a6, R);
        float Rn[9];
#pragma unroll
        for (int i = 0; i < 3; ++i)
#pragma unroll
            for (int k = 0; k < 3; ++k)
                Rn[3 * i + k] = Rc[3 * i + 0] * R[0 + k]
                              + Rc[3 * i + 1] * R[3 + k]
                              + Rc[3 * i + 2] * R[6 + k];
        float tx = stv[3 * c + 0], ty = stv[3 * c + 1], tz = stv[3 * c + 2];
        pw[3 * c + 0] = Rn[0] * tx + Rn[1] * ty + Rn[2] * tz + pw[3 * p + 0];
        pw[3 * c + 1] = Rn[3] * tx + Rn[4] * ty + Rn[5] * tz + pw[3 * p + 1];
        pw[3 * c + 2] = Rn[6] * tx + Rn[7] * ty + Rn[8] * tz + pw[3 * p + 2];
#pragma unroll
        for (int i = 0; i < 9; ++i) Rc[i] = Rn[i];
    };

    // ---- Phase 1: joints 0-7, pw[0..23] stays in registers ----
    loadRows(0);                             // joints 0,1
    rot6d(&a2[0], Rc);
    {
        float x = stv[0], y = stv[1], z = stv[2];
        pw[0] = Rc[0] * x + Rc[1] * y + Rc[2] * z;
        pw[1] = Rc[3] * x + Rc[4] * y + Rc[5] * z;
        pw[2] = Rc[6] * x + Rc[7] * y + Rc[8] * z;
    }
    step(0, 1, &a2[6]);
    loadRows(3);                             // joints 2,3
    step(1, 2, &a2[0]);
    step(2, 3, &a2[6]);
#pragma unroll
    for (int i = 0; i < 9; ++i) Rs[i] = Rc[i];   // Rw3

    loadRows(6);                             // joints 4,5 (branch A)
    step(3, 4, &a2[0]);
    step(4, 5, &a2[6]);

#pragma unroll
    for (int i = 0; i < 9; ++i) Rc[i] = Rs[i];
    loadRows(9);                             // joints 6,7 (branch B start)
    step(3, 6, &a2[0]);
    step(6, 7, &a2[6]);
    // Rc = Rw7 carried across the restage.

    __syncthreads();                         // S2: all half-0 reads done

    // ---- Stage half 1: joints 8-15 (element float4s 12..23) into same rows ----
#pragma unroll
    for (int k = 0; k < 12; ++k) {
        int g = t + k * TPB;
        int b = g / 12;
        int r = g - b * 12;
        sa4[r * PIT + b] = __ldg(src + b * 24 + 12 + r);
    }
    __syncthreads();                         // S3: half 1 visible

    // ---- Phase 2: joints 8-15; flush all 12 pw rows into consumed rows ----
    loadRows(0);                             // joints 8,9
    flushRow(0); flushRow(1); flushRow(2);   // pw[0..11] -> regs freed
    step(7, 8, &a2[0]);
    step(8, 9, &a2[6]);

    loadRows(3);                             // joints 10,11
    flushRow(3); flushRow(4); flushRow(5);   // pw[12..23] -> regs freed
    step(9, 10, &a2[0]);
#pragma unroll
    for (int i = 0; i < 9; ++i) Rc[i] = Rs[i];   // branch C from Rw3
    step(3, 11, &a2[6]);

    loadRows(6);                             // joints 12,13
    flushRow(6); flushRow(7); flushRow(8);   // pw[24..35] ready
    step(11, 12, &a2[0]);
    step(12, 13, &a2[6]);

    loadRows(9);                             // joints 14,15
    flushRow(9);                             // pw[36..39] ready
    step(13, 14, &a2[0]);
    flushRow(10);                            // pw[40..43] ready
    step(14, 15, &a2[6]);
    flushRow(11);                            // pw[44..47] ready

    __syncthreads();                         // S4: pw rows complete

    // ---- Gather: conflict-free LDS.128 -> coalesced STG.128 ----
    float4* __restrict__ dst = out4 + tile * 12;
#pragma unroll
    for (int k = 0; k < 12; ++k) {
        int g = t + k * TPB;                 // 0..1535
        int b = g / 12;
        int r = g - b * 12;
        dst[g] = sa4[r * PIT + b];
    }
}

// Tail fallback (unused: 262144 % 128 == 0; kept for safety).
__global__ void skeleton_fk_tail(const float* __restrict__ angles,
                                 const float* __restrict__ xyz,
                                 float* __restrict__ out,
                                 int start, int batch)
{
    int b = start + blockIdx.x * blockDim.x + threadIdx.x;
    if (b >= batch) return;
    const float* ab = angles + (size_t)b * (NJ * 6);
    float ref[NJ * 3];
#pragma unroll
    for (int i = 0; i < NJ * 3; ++i) ref[i] = __ldg(xyz + i);

    float Rw[NJ * 9], pw[NJ * 3];
    {
        float a[6];
#pragma unroll
        for (int k = 0; k < 6; ++k) a[k] = ab[k];
        rot6d(a, &Rw[0]);
        float x = ref[0], y = ref[1], z = ref[2];
        pw[0] = Rw[0] * x + Rw[1] * y + Rw[2] * z;
        pw[1] = Rw[3] * x + Rw[4] * y + Rw[5] * z;
        pw[2] = Rw[6] * x + Rw[7] * y + Rw[8] * z;
    }
    constexpr int PARENT[15] = {0, 1, 2, 3, 4, 3, 6, 7, 8, 9, 3, 11, 12, 13, 14};
#pragma unroll
    for (int e = 0; e < 15; ++e) {
        const int p = PARENT[e], c = e + 1;
        float a[6];
#pragma unroll
        for (int k = 0; k < 6; ++k) a[k] = ab[6 * c + k];
        float R[9]; rot6d(a, R);
        float tx = ref[3 * c + 0] - ref[3 * p + 0];
        float ty = ref[3 * c + 1] - ref[3 * p + 1];
        float tz = ref[3 * c + 2] - ref[3 * p + 2];
        const float* pR = &Rw[9 * p];
        float* nR = &Rw[9 * c];
#pragma unroll
        for (int i = 0; i < 3; ++i)
#pragma unroll
            for (int k = 0; k < 3; ++k)
                nR[3 * i + k] = pR[3 * i + 0] * R[k] + pR[3 * i + 1] * R[3 + k]
                              + pR[3 * i + 2] * R[6 + k];
        pw[3 * c + 0] = nR[0] * tx + nR[1] * ty + nR[2] * tz + pw[3 * p + 0];
        pw[3 * c + 1] = nR[3] * tx + nR[4] * ty + nR[5] * tz + pw[3 * p + 1];
        pw[3 * c + 2] = nR[6] * tx + nR[7] * ty + nR[8] * tz + pw[3 * p + 2];
    }
    float* o = out + (size_t)b * (NJ * 3);
#pragma unroll
    for (int i = 0; i < NJ * 3; ++i) o[i] = pw[i];
}

}  // namespace

extern "C" void kernel_launch(void* const* d_in, const int* in_sizes, int n_in,
                              void* d_out, int out_size) {
    const float* angles = (const float*)d_in[0];
    const float* xyz    = (const float*)d_in[1];
    float* out          = (float*)d_out;

    const int batch = in_sizes[0] / (NJ * 6);
    const int full  = batch / TPB;

    cudaFuncSetAttribute(skeleton_fk_v16,
                         cudaFuncAttributeMaxDynamicSharedMemorySize,
                         (int)SMEM_BYTES);

    if (full > 0) {
        skeleton_fk_v16<<<full, TPB, SMEM_BYTES>>>(
            (const float4*)angles, xyz, (float4*)out);
    }
    const int rem = batch - full * TPB;
    if (rem > 0) {
        skeleton_fk_tail<<<(rem + 127) / 128, 128>>>(angles, xyz, out,
                                                     full * TPB, batch);
    }
}